// round 2
// baseline (speedup 1.0000x reference)
#include <cuda_runtime.h>
#include <cstdint>

#define H 1024
#define W 1024
#define D 128
#define K 2048
#define NCAP (1 << 20)      // candidate buffer capacity (worst case: every pixel)
#define SELCAP 4096         // post-threshold selection capacity (expect ~K + few)
#define NEG_INF __int_as_float(0xFF800000)

// ---------------- scratch (static device globals; no allocation) ----------------
__device__ unsigned long long g_cand[NCAP];
__device__ unsigned long long g_sel[SELCAP];
__device__ int g_ncand;
__device__ int g_nsel;
__device__ unsigned int g_hist1[2048];
__device__ unsigned int g_hist2[2048];
__device__ int g_b1;
__device__ unsigned int g_above1;
__device__ unsigned int g_tmin;
__device__ int g_topidx[K];

// ordered key for positive floats (all candidates have v > 0): set sign bit.
// Preserves ordering; pad key 0 sorts below every candidate.
__device__ __forceinline__ unsigned int ordkey(float v) {
    return __float_as_uint(v) | 0x80000000u;
}

// ---------------- kernel 0: zero counters + histograms -------------------------
__global__ void k_init() {
    int i = blockIdx.x * blockDim.x + threadIdx.x;
    if (i < 2048) { g_hist1[i] = 0; g_hist2[i] = 0; }
    if (i == 0) { g_ncand = 0; g_nsel = 0; }
}

// ---------------- kernel 1: NMS candidate detection + level-1 histogram --------
__global__ __launch_bounds__(1024) void k_detect(const float* __restrict__ heat,
                                                 const int* __restrict__ ow_p,
                                                 const int* __restrict__ oh_p) {
    __shared__ float tile[36][37];
    const int bx = blockIdx.x * 32;
    const int by = blockIdx.y * 32;
    const int lx = threadIdx.x, ly = threadIdx.y;
    // load 36x36 halo tile
    for (int i = ly * 32 + lx; i < 36 * 36; i += 1024) {
        int ty = i / 36, tx = i % 36;
        int gy = by + ty - 2, gx = bx + tx - 2;
        float v = (gx >= 0 && gx < W && gy >= 0 && gy < H) ? heat[gy * W + gx] : NEG_INF;
        tile[ty][tx] = v;
    }
    __syncthreads();

    float v = tile[ly + 2][lx + 2];
    float m = NEG_INF;
#pragma unroll
    for (int dy = 0; dy < 5; dy++)
#pragma unroll
        for (int dx = 0; dx < 5; dx++)
            m = fmaxf(m, tile[ly + dy][lx + dx]);

    int x = bx + lx, y = by + ly;
    int ow = ow_p ? __ldg(ow_p) : W;
    int oh = oh_p ? __ldg(oh_p) : H;
    if (v > 0.0f && v == m && x <= ow - 1 && y <= oh - 1) {
        unsigned int uk = ordkey(v);
        unsigned int idx = (unsigned int)(y * W + x);
        unsigned long long key = ((unsigned long long)uk << 32) | (0xFFFFFFFFu - idx);
        int pos = atomicAdd(&g_ncand, 1);
        if (pos < NCAP) g_cand[pos] = key;
        atomicAdd(&g_hist1[uk >> 21], 1u);
    }
}

// ---------------- suffix-scan helper (2048 bins, 1024 threads) ------------------
__device__ void suffix_scan_2048(unsigned int* s, int tid) {
    for (int off = 1; off < 2048; off <<= 1) {
        unsigned int a0 = (tid + off < 2048) ? s[tid + off] : 0u;
        unsigned int a1 = (tid + 1024 + off < 2048) ? s[tid + 1024 + off] : 0u;
        __syncthreads();
        s[tid] += a0;
        s[tid + 1024] += a1;
        __syncthreads();
    }
}

// ---------------- kernel 2: find boundary bin of level-1 histogram --------------
__global__ __launch_bounds__(1024) void k_scan1() {
    __shared__ unsigned int s[2048];
    int tid = threadIdx.x;
    s[tid] = g_hist1[tid];
    s[tid + 1024] = g_hist1[tid + 1024];
    __syncthreads();
    suffix_scan_2048(s, tid);
    // s[b] = count of keys with top11 >= b  (non-increasing in b)
    for (int b = tid; b < 2048; b += 1024) {
        if (s[b] >= K && (b == 2047 || s[b + 1] < K)) {
            g_b1 = b;
            g_above1 = (b < 2047) ? s[b + 1] : 0u;
        }
    }
    if (tid == 0 && s[0] < K) {  // fewer than K candidates total: select all
        g_b1 = 0;
        g_above1 = 0;
    }
}

// ---------------- kernel 3: level-2 histogram over boundary bin -----------------
__global__ void k_hist2() {
    int n = min(g_ncand, NCAP);
    int b1 = g_b1;
    for (int i = blockIdx.x * blockDim.x + threadIdx.x; i < n; i += gridDim.x * blockDim.x) {
        unsigned int hi = (unsigned int)(g_cand[i] >> 32);
        if ((int)(hi >> 21) == b1)
            atomicAdd(&g_hist2[(hi >> 10) & 0x7FFu], 1u);
    }
}

// ---------------- kernel 4: refine threshold --------------------------------------
__global__ __launch_bounds__(1024) void k_scan2() {
    __shared__ unsigned int s[2048];
    int tid = threadIdx.x;
    s[tid] = g_hist2[tid];
    s[tid + 1024] = g_hist2[tid + 1024];
    __syncthreads();
    suffix_scan_2048(s, tid);
    unsigned int above1 = g_above1;
    unsigned int b1 = (unsigned int)g_b1;
    for (int b = tid; b < 2048; b += 1024) {
        if (above1 + s[b] >= K && (b == 2047 || above1 + s[b + 1] < K)) {
            g_tmin = (b1 << 21) | ((unsigned int)b << 10);
        }
    }
    if (tid == 0 && above1 + s[0] < K) {  // whole bin b1 still < K: take all of it
        g_tmin = (b1 << 21);
    }
}

// ---------------- kernel 5: compact survivors -------------------------------------
__global__ void k_compact() {
    int n = min(g_ncand, NCAP);
    unsigned int tmin = g_tmin;
    for (int i = blockIdx.x * blockDim.x + threadIdx.x; i < n; i += gridDim.x * blockDim.x) {
        unsigned long long key = g_cand[i];
        if ((unsigned int)(key >> 32) >= tmin) {
            int pos = atomicAdd(&g_nsel, 1);
            if (pos < SELCAP) g_sel[pos] = key;
        }
    }
}

// ---------------- kernel 6: single-block bitonic sort + emit kp/scores/valid ------
// Output layout (float32): keypoints[K,2] | scores[K] | d[K,D] | valid[K]
#define OUT_KP 0
#define OUT_SC (K * 2)
#define OUT_D (K * 2 + K)
#define OUT_VALID (K * 2 + K + K * D)

__global__ __launch_bounds__(1024) void k_sort(float* __restrict__ out) {
    __shared__ unsigned long long s[SELCAP];
    int tid = threadIdx.x;
    int n = min(g_nsel, SELCAP);
    for (int i = tid; i < SELCAP; i += 1024)
        s[i] = (i < n) ? g_sel[i] : 0ull;
    __syncthreads();
    // bitonic sort descending (larger key = better: value desc, then idx asc)
    for (unsigned int k = 2; k <= SELCAP; k <<= 1) {
        for (unsigned int j = k >> 1; j > 0; j >>= 1) {
            for (unsigned int i = tid; i < SELCAP; i += 1024) {
                unsigned int l = i ^ j;
                if (l > i) {
                    unsigned long long a = s[i], b = s[l];
                    bool desc = ((i & k) == 0);
                    if (desc ? (a < b) : (a > b)) { s[i] = b; s[l] = a; }
                }
            }
            __syncthreads();
        }
    }
    for (int r = tid; r < K; r += 1024) {
        unsigned long long key = s[r];
        unsigned int hi = (unsigned int)(key >> 32);
        unsigned int lo = (unsigned int)key;
        if (key != 0ull) {
            unsigned int idx = 0xFFFFFFFFu - lo;
            int x = (int)(idx % W);
            int y = (int)(idx / W);
            out[OUT_KP + 2 * r + 0] = (float)x;
            out[OUT_KP + 2 * r + 1] = (float)y;
            out[OUT_SC + r] = __uint_as_float(hi & 0x7FFFFFFFu);  // clear sign bit back
            out[OUT_VALID + r] = 1.0f;
            g_topidx[r] = (int)idx;
        } else {
            // fewer than K candidates (does not occur for this input); pad like top_k of -inf
            out[OUT_KP + 2 * r + 0] = 0.0f;
            out[OUT_KP + 2 * r + 1] = 0.0f;
            out[OUT_SC + r] = NEG_INF;
            out[OUT_VALID + r] = 0.0f;
            g_topidx[r] = 0;
        }
    }
}

// ---------------- kernel 7: descriptor gather + L2 normalize ---------------------
__global__ __launch_bounds__(128) void k_gather(const float* __restrict__ feat,
                                                float* __restrict__ out) {
    int r = blockIdx.x;
    int c = threadIdx.x;
    int idx = g_topidx[r];
    float v = __ldg(&feat[(size_t)c * (H * W) + idx]);
    // block reduce sum of squares over 128 threads (4 warps)
    float ss = v * v;
#pragma unroll
    for (int o = 16; o > 0; o >>= 1) ss += __shfl_down_sync(0xFFFFFFFFu, ss, o);
    __shared__ float ws[4];
    if ((c & 31) == 0) ws[c >> 5] = ss;
    __syncthreads();
    float total = ws[0] + ws[1] + ws[2] + ws[3];
    float norm = fmaxf(sqrtf(total), 1e-12f);
    out[OUT_D + (size_t)r * D + c] = v / norm;
}

// ---------------- launch ---------------------------------------------------------
extern "C" void kernel_launch(void* const* d_in, const int* in_sizes, int n_in,
                              void* d_out, int out_size) {
    const float* feat = (const float*)d_in[0];
    const int* ow_p = (n_in > 1) ? (const int*)d_in[1] : nullptr;
    const int* oh_p = (n_in > 2) ? (const int*)d_in[2] : nullptr;
    float* out = (float*)d_out;
    const float* heat = feat + (size_t)D * H * W;  // channel D is the heatmap

    k_init<<<2, 1024>>>();
    k_detect<<<dim3(W / 32, H / 32), dim3(32, 32)>>>(heat, ow_p, oh_p);
    k_scan1<<<1, 1024>>>();
    k_hist2<<<256, 256>>>();
    k_scan2<<<1, 1024>>>();
    k_compact<<<256, 256>>>();
    k_sort<<<1, 1024>>>(out);
    k_gather<<<K, 128>>>(feat, out);
}

// round 3
// speedup vs baseline: 1.5917x; 1.5917x over previous
#include <cuda_runtime.h>
#include <cstdint>

#define H 1024
#define W 1024
#define D 128
#define K 2048
#define NCAP (1 << 20)
#define SELCAP 4096
#define NB 128            // blocks; <= 148 SMs so all co-resident
#define NT 1024
#define NEG_INF __int_as_float(0xFF800000)

// Output layout (float32): keypoints[K,2] | scores[K] | d[K,D] | valid[K]
#define OUT_KP 0
#define OUT_SC (K * 2)
#define OUT_D (K * 2 + K)
#define OUT_VALID (K * 2 + K + K * D)

// ---------------- scratch (static device globals; no allocation) ----------------
__device__ unsigned long long g_cand[NCAP];
__device__ unsigned long long g_sel[SELCAP];
__device__ int g_ncand;
__device__ int g_nsel;
__device__ unsigned int g_hist1[2048];
__device__ unsigned int g_hist2[2048];
__device__ int g_b1;
__device__ unsigned int g_above1;
__device__ unsigned int g_tmin;
__device__ int g_topidx[K];
__device__ unsigned int g_barcnt;           // barrier arrival counter
__device__ volatile unsigned int g_bargen;  // barrier generation (monotonic across replays)

// ---------------- shared memory union (per-phase reuse) ----------------
struct DetSm {
    float tile[36][37];
    float rowmax[36][32];
    unsigned long long list[1024];
    int cnt;
    int base;
};
struct ScanSm { unsigned int s[2048]; };
struct RankSm { unsigned long long keys[SELCAP]; };
struct GthSm  { float ws[8][4]; };
union SmU { DetSm det; ScanSm scan; RankSm rank; GthSm g; };

// ---------------- software grid barrier (all NB blocks resident) ----------------
__device__ __forceinline__ void gbar() {
    __syncthreads();
    if (threadIdx.x == 0) {
        unsigned int gen = g_bargen;      // read BEFORE arriving
        __threadfence();                  // release prior writes
        if (atomicAdd(&g_barcnt, 1u) == NB - 1) {
            g_barcnt = 0;
            __threadfence();
            g_bargen = gen + 1;           // wake everyone
        } else {
            while (g_bargen == gen) { }
        }
        __threadfence();                  // acquire
    }
    __syncthreads();
}

__device__ __forceinline__ void suffix_scan_2048(unsigned int* s, int tid) {
    for (int off = 1; off < 2048; off <<= 1) {
        unsigned int a0 = (tid + off < 2048) ? s[tid + off] : 0u;
        unsigned int a1 = (tid + 1024 + off < 2048) ? s[tid + 1024 + off] : 0u;
        __syncthreads();
        s[tid] += a0;
        s[tid + 1024] += a1;
        __syncthreads();
    }
}

__global__ __launch_bounds__(NT, 1) void disk_mega(const float* __restrict__ feat,
                                                   const int* __restrict__ ow_p,
                                                   const int* __restrict__ oh_p,
                                                   float* __restrict__ out) {
    __shared__ SmU sm;
    const int tid = threadIdx.x;
    const int gid = blockIdx.x * NT + tid;
    const float* heat = feat + (size_t)D * H * W;
    const int ow = ow_p ? __ldg(ow_p) : W;
    const int oh = oh_p ? __ldg(oh_p) : H;

    // ========== phase 0: init ==========
    if (gid < 2048) { g_hist1[gid] = 0u; g_hist2[gid] = 0u; }
    if (gid == 0) { g_ncand = 0; g_nsel = 0; }
    gbar();

    // ========== phase 1: NMS detect (separable 5x5 max, per-tile aggregation) ====
    {
        const int lx = tid & 31, ly = tid >> 5;
        for (int t = blockIdx.x; t < (H / 32) * (W / 32); t += NB) {
            const int bx = (t & 31) * 32, by = (t >> 5) * 32;
            // load 36x36 halo
            for (int i = tid; i < 36 * 36; i += NT) {
                int ty = i / 36, tx = i - ty * 36;
                int gy = by + ty - 2, gx = bx + tx - 2;
                sm.det.tile[ty][tx] =
                    (gx >= 0 && gx < W && gy >= 0 && gy < H) ? heat[gy * W + gx] : NEG_INF;
            }
            if (tid == 0) sm.det.cnt = 0;
            __syncthreads();
            // horizontal 5-max
            for (int i = tid; i < 36 * 32; i += NT) {
                int ty = i >> 5, tx = i & 31;
                float m = sm.det.tile[ty][tx];
                m = fmaxf(m, sm.det.tile[ty][tx + 1]);
                m = fmaxf(m, sm.det.tile[ty][tx + 2]);
                m = fmaxf(m, sm.det.tile[ty][tx + 3]);
                m = fmaxf(m, sm.det.tile[ty][tx + 4]);
                sm.det.rowmax[ty][tx] = m;
            }
            __syncthreads();
            // vertical 5-max + candidate test
            float v = sm.det.tile[ly + 2][lx + 2];
            float m = sm.det.rowmax[ly][lx];
            m = fmaxf(m, sm.det.rowmax[ly + 1][lx]);
            m = fmaxf(m, sm.det.rowmax[ly + 2][lx]);
            m = fmaxf(m, sm.det.rowmax[ly + 3][lx]);
            m = fmaxf(m, sm.det.rowmax[ly + 4][lx]);
            int x = bx + lx, y = by + ly;
            if (v > 0.0f && v == m && x <= ow - 1 && y <= oh - 1) {
                unsigned int uk = __float_as_uint(v) | 0x80000000u;  // ordered key (v>0)
                unsigned int idx = (unsigned int)(y * W + x);
                unsigned long long key =
                    ((unsigned long long)uk << 32) | (0xFFFFFFFFu - idx);
                int p = atomicAdd(&sm.det.cnt, 1);
                sm.det.list[p] = key;
                atomicAdd(&g_hist1[uk >> 21], 1u);
            }
            __syncthreads();
            if (tid == 0) sm.det.base = atomicAdd(&g_ncand, sm.det.cnt);
            __syncthreads();
            const int cnt = sm.det.cnt, base = sm.det.base;
            for (int i = tid; i < cnt; i += NT) g_cand[base + i] = sm.det.list[i];
            __syncthreads();
        }
    }
    gbar();

    // ========== phase 2: level-1 suffix scan -> boundary bin (block 0) ==========
    if (blockIdx.x == 0) {
        sm.scan.s[tid] = __ldcg(&g_hist1[tid]);
        sm.scan.s[tid + 1024] = __ldcg(&g_hist1[tid + 1024]);
        __syncthreads();
        suffix_scan_2048(sm.scan.s, tid);
        for (int b = tid; b < 2048; b += NT) {
            if (sm.scan.s[b] >= K && (b == 2047 || sm.scan.s[b + 1] < K)) {
                g_b1 = b;
                g_above1 = (b < 2047) ? sm.scan.s[b + 1] : 0u;
            }
        }
        if (tid == 0 && sm.scan.s[0] < K) { g_b1 = 0; g_above1 = 0u; }
    }
    gbar();

    // ========== phase 3: level-2 histogram over boundary bin (all blocks) =======
    {
        const int n = min(__ldcg(&g_ncand), NCAP);
        const int b1 = __ldcg(&g_b1);
        for (int i = gid; i < n; i += NB * NT) {
            unsigned int hi = (unsigned int)(__ldcg(&g_cand[i]) >> 32);
            if ((int)(hi >> 21) == b1) atomicAdd(&g_hist2[(hi >> 10) & 0x7FFu], 1u);
        }
    }
    gbar();

    // ========== phase 4: level-2 suffix scan -> threshold (block 0) =============
    if (blockIdx.x == 0) {
        sm.scan.s[tid] = __ldcg(&g_hist2[tid]);
        sm.scan.s[tid + 1024] = __ldcg(&g_hist2[tid + 1024]);
        __syncthreads();
        suffix_scan_2048(sm.scan.s, tid);
        const unsigned int above1 = __ldcg(&g_above1);
        const unsigned int b1 = (unsigned int)__ldcg(&g_b1);
        for (int b = tid; b < 2048; b += NT) {
            if (above1 + sm.scan.s[b] >= K &&
                (b == 2047 || above1 + sm.scan.s[b + 1] < K)) {
                g_tmin = (b1 << 21) | ((unsigned int)b << 10);
            }
        }
        if (tid == 0 && above1 + sm.scan.s[0] < K) g_tmin = (b1 << 21);
    }
    gbar();

    // ========== phase 5: compact survivors (warp-aggregated atomics) ============
    {
        const int n = min(__ldcg(&g_ncand), NCAP);
        const unsigned int tmin = __ldcg(&g_tmin);
        const int stride = NB * NT;
        const int niter = (n + stride - 1) / stride;
        const int lane = tid & 31;
        for (int t = 0; t < niter; t++) {
            int i = gid + t * stride;
            unsigned long long key = 0ull;
            bool keep = false;
            if (i < n) {
                key = __ldcg(&g_cand[i]);
                keep = ((unsigned int)(key >> 32)) >= tmin;
            }
            unsigned int mask = __ballot_sync(0xFFFFFFFFu, keep);
            if (mask) {
                int leader = __ffs(mask) - 1;
                int base = 0;
                if (lane == leader) base = atomicAdd(&g_nsel, __popc(mask));
                base = __shfl_sync(0xFFFFFFFFu, base, leader);
                if (keep) {
                    int off = __popc(mask & ((1u << lane) - 1u));
                    if (base + off < SELCAP) g_sel[base + off] = key;
                }
            }
        }
    }
    gbar();

    // ========== phase 6: exact rank (one warp per survivor) + emit ==============
    {
        const int nsel = min(__ldcg(&g_nsel), SELCAP);
        for (int i = tid; i < nsel; i += NT) sm.rank.keys[i] = __ldcg(&g_sel[i]);
        __syncthreads();
        const int w = tid >> 5, lane = tid & 31;
        const int gi = blockIdx.x * 32 + w;  // 128*32 = 4096 slots
        if (gi < nsel) {
            const unsigned long long key = sm.rank.keys[gi];
            unsigned int cnt = 0;
            for (int j = lane; j < nsel; j += 32)
                cnt += (sm.rank.keys[j] > key) ? 1u : 0u;
            cnt = __reduce_add_sync(0xFFFFFFFFu, cnt);  // exact rank (keys unique)
            if (lane == 0 && cnt < K) {
                unsigned int hi = (unsigned int)(key >> 32);
                unsigned int idx = 0xFFFFFFFFu - (unsigned int)key;
                out[OUT_KP + 2 * cnt + 0] = (float)(idx & (W - 1));
                out[OUT_KP + 2 * cnt + 1] = (float)(idx >> 10);
                out[OUT_SC + cnt] = __uint_as_float(hi & 0x7FFFFFFFu);
                out[OUT_VALID + cnt] = 1.0f;
                g_topidx[cnt] = (int)idx;
            }
        } else if (gi < K && lane == 0) {  // padding when nsel < K
            out[OUT_KP + 2 * gi + 0] = 0.0f;
            out[OUT_KP + 2 * gi + 1] = 0.0f;
            out[OUT_SC + gi] = NEG_INF;
            out[OUT_VALID + gi] = 0.0f;
            g_topidx[gi] = 0;
        }
    }
    gbar();

    // ========== phase 7: descriptor gather + L2 normalize =======================
    {
        const int c = tid & 127;     // descriptor channel
        const int sub = tid >> 7;    // 0..7 rows per block
        for (int r = blockIdx.x * 8 + sub; r < K; r += NB * 8) {
            const int idx = __ldcg(&g_topidx[r]);
            const float v = __ldg(&feat[(size_t)c * (H * W) + idx]);
            float ss = v * v;
#pragma unroll
            for (int o = 16; o > 0; o >>= 1) ss += __shfl_down_sync(0xFFFFFFFFu, ss, o);
            if ((c & 31) == 0) sm.g.ws[sub][c >> 5] = ss;
            __syncthreads();
            const float tot = sm.g.ws[sub][0] + sm.g.ws[sub][1] +
                              sm.g.ws[sub][2] + sm.g.ws[sub][3];
            const float norm = fmaxf(sqrtf(tot), 1e-12f);
            out[OUT_D + (size_t)r * D + c] = v / norm;
            __syncthreads();
        }
    }
}

// ---------------- launch ---------------------------------------------------------
extern "C" void kernel_launch(void* const* d_in, const int* in_sizes, int n_in,
                              void* d_out, int out_size) {
    const float* feat = (const float*)d_in[0];
    const int* ow_p = (n_in > 1) ? (const int*)d_in[1] : nullptr;
    const int* oh_p = (n_in > 2) ? (const int*)d_in[2] : nullptr;
    float* out = (float*)d_out;
    disk_mega<<<NB, NT>>>(feat, ow_p, oh_p, out);
}

// round 7
// speedup vs baseline: 1.9364x; 1.2165x over previous
#include <cuda_runtime.h>
#include <cstdint>

#define H 1024
#define W 1024
#define D 128
#define K 2048
#define NCAP (1 << 20)
#define SELCAP 4096
#define NB 128            // blocks; <= 148 SMs so all co-resident
#define NT 1024
#define NEG_INF __int_as_float(0xFF800000)

// Output layout (float32): keypoints[K,2] | scores[K] | d[K,D] | valid[K]
#define OUT_KP 0
#define OUT_SC (K * 2)
#define OUT_D (K * 2 + K)
#define OUT_VALID (K * 2 + K + K * D)

// ---------------- scratch (static device globals; no allocation) ----------------
__device__ unsigned long long g_cand[NCAP];
__device__ unsigned long long g_sel[SELCAP];
__device__ int g_ncand;
__device__ int g_nsel;
__device__ unsigned int g_hist1[2048];
__device__ unsigned int g_hist2[2048];
__device__ unsigned int g_barcnt;
__device__ volatile unsigned int g_bargen;
__device__ unsigned int g_done;

// ---------------- shared memory union (per-phase reuse) ----------------
struct __align__(16) DetSm {
    float tile[36][44];     // halo cols [bx-4, bx+36), row width padded
    float rowmax[36][33];
    unsigned long long list[1024];
    int cnt;
    int base;
};
struct ScanSm { unsigned int s[2048]; };
struct RankSm { unsigned long long keys[SELCAP]; };
union SmU { DetSm det; ScanSm scan; RankSm rank; };

// ---------------- software grid barrier (all NB blocks resident) ----------------
__device__ __forceinline__ void gbar() {
    __syncthreads();
    if (threadIdx.x == 0) {
        unsigned int gen = g_bargen;
        __threadfence();
        if (atomicAdd(&g_barcnt, 1u) == NB - 1) {
            g_barcnt = 0;
            __threadfence();
            g_bargen = gen + 1;
        } else {
            while (g_bargen == gen) { }
        }
        __threadfence();
    }
    __syncthreads();
}

__device__ __forceinline__ void suffix_scan_2048(unsigned int* s, int tid) {
    for (int off = 1; off < 2048; off <<= 1) {
        unsigned int a0 = (tid + off < 2048) ? s[tid + off] : 0u;
        unsigned int a1 = (tid + 1024 + off < 2048) ? s[tid + 1024 + off] : 0u;
        __syncthreads();
        s[tid] += a0;
        s[tid + 1024] += a1;
        __syncthreads();
    }
}

__global__ __launch_bounds__(NT, 1) void disk_mega(const float* __restrict__ feat,
                                                   const int* __restrict__ ow_p,
                                                   const int* __restrict__ oh_p,
                                                   float* __restrict__ out) {
    __shared__ SmU sm;
    __shared__ unsigned int sb1, sabove1, stmin;
    __shared__ int slast;
    const int tid = threadIdx.x;
    const int gid = blockIdx.x * NT + tid;
    const float* heat = feat + (size_t)D * H * W;
    const int ow = ow_p ? __ldg(ow_p) : W;
    const int oh = oh_p ? __ldg(oh_p) : H;

    // ========== phase 1: NMS detect (vectorized halo, separable 5x5) ============
    // Counters & histograms are zero on entry: statics start zeroed; the tail of
    // every run re-zeros ALL of them (stride loop!) for the next graph replay.
    {
        const int lx = tid & 31, ly = tid >> 5;
        for (int t = blockIdx.x; t < (H / 32) * (W / 32); t += NB) {
            const int bx = (t & 31) * 32, by = (t >> 5) * 32;
            // halo load: 36 rows x 10 float4 (cols bx-4 .. bx+35), 16B-aligned
            if (tid < 360) {
                const int r = tid / 10, c = tid - r * 10;
                const int gy = by - 2 + r;
                const int gx0 = bx - 4 + c * 4;
                float4 v;
                if (gy >= 0 && gy < H && gx0 >= 0 && gx0 < W)
                    v = *(const float4*)(heat + (size_t)gy * W + gx0);
                else
                    v = make_float4(NEG_INF, NEG_INF, NEG_INF, NEG_INF);
                *(float4*)&sm.det.tile[r][c * 4] = v;
            }
            if (tid == 0) sm.det.cnt = 0;
            __syncthreads();
            // horizontal 5-max: output col p corresponds to center tx+4
            for (int i = tid; i < 36 * 32; i += NT) {
                const int ty = i >> 5, tx = i & 31;
                const float* row = sm.det.tile[ty];
                float m = fmaxf(fmaxf(fmaxf(row[tx + 2], row[tx + 3]),
                                      fmaxf(row[tx + 4], row[tx + 5])),
                                row[tx + 6]);
                sm.det.rowmax[ty][tx] = m;
            }
            __syncthreads();
            // vertical 5-max + candidate test
            const float v = sm.det.tile[ly + 2][lx + 4];
            float m = fmaxf(fmaxf(fmaxf(sm.det.rowmax[ly][lx], sm.det.rowmax[ly + 1][lx]),
                                  fmaxf(sm.det.rowmax[ly + 2][lx], sm.det.rowmax[ly + 3][lx])),
                            sm.det.rowmax[ly + 4][lx]);
            const int x = bx + lx, y = by + ly;
            if (v > 0.0f && v == m && x <= ow - 1 && y <= oh - 1) {
                const unsigned int uk = __float_as_uint(v) | 0x80000000u;
                const unsigned int idx = (unsigned int)(y * W + x);
                const unsigned long long key =
                    ((unsigned long long)uk << 32) | (0xFFFFFFFFu - idx);
                const int p = atomicAdd(&sm.det.cnt, 1);
                sm.det.list[p] = key;
                atomicAdd(&g_hist1[uk >> 21], 1u);
            }
            __syncthreads();
            if (tid == 0) sm.det.base = atomicAdd(&g_ncand, sm.det.cnt);
            __syncthreads();
            const int cnt = sm.det.cnt, base = sm.det.base;
            for (int i = tid; i < cnt; i += NT) g_cand[base + i] = sm.det.list[i];
            __syncthreads();
        }
    }
    gbar();

    // ========== phase 2: redundant per-block scan1 -> b1; then hist2 ============
    {
        sm.scan.s[tid] = __ldcg(&g_hist1[tid]);
        sm.scan.s[tid + 1024] = __ldcg(&g_hist1[tid + 1024]);
        __syncthreads();
        suffix_scan_2048(sm.scan.s, tid);
        for (int b = tid; b < 2048; b += NT) {
            if (sm.scan.s[b] >= K && (b == 2047 || sm.scan.s[b + 1] < K)) {
                sb1 = (unsigned int)b;
                sabove1 = (b < 2047) ? sm.scan.s[b + 1] : 0u;
            }
        }
        if (tid == 0 && sm.scan.s[0] < K) { sb1 = 0u; sabove1 = 0u; }
        __syncthreads();
        const unsigned int b1 = sb1;
        const int n = min(__ldcg(&g_ncand), NCAP);
        for (int i = gid; i < n; i += NB * NT) {
            const unsigned int hi = (unsigned int)(__ldcg(&g_cand[i]) >> 32);
            if ((hi >> 21) == b1) atomicAdd(&g_hist2[(hi >> 10) & 0x7FFu], 1u);
        }
    }
    gbar();

    // ========== phase 3: redundant per-block scan2 -> tmin; then compact ========
    {
        const unsigned int above1 = sabove1;   // survives in shared across gbar
        const unsigned int b1 = sb1;
        sm.scan.s[tid] = __ldcg(&g_hist2[tid]);
        sm.scan.s[tid + 1024] = __ldcg(&g_hist2[tid + 1024]);
        __syncthreads();
        suffix_scan_2048(sm.scan.s, tid);
        for (int b = tid; b < 2048; b += NT) {
            if (above1 + sm.scan.s[b] >= K &&
                (b == 2047 || above1 + sm.scan.s[b + 1] < K)) {
                stmin = (b1 << 21) | ((unsigned int)b << 10);
            }
        }
        if (tid == 0 && above1 + sm.scan.s[0] < K) stmin = (b1 << 21);
        __syncthreads();
        const unsigned int tmin = stmin;
        const int n = min(__ldcg(&g_ncand), NCAP);
        const int stride = NB * NT;
        const int niter = (n + stride - 1) / stride;   // UNIFORM trip count
        const int lane = tid & 31;
        for (int t = 0; t < niter; t++) {
            const int i = gid + t * stride;
            unsigned long long key = 0ull;
            bool keep = false;
            if (i < n) {
                key = __ldcg(&g_cand[i]);
                keep = ((unsigned int)(key >> 32)) >= tmin;
            }
            const unsigned int mask = __ballot_sync(0xFFFFFFFFu, keep);
            if (mask) {
                const int leader = __ffs(mask) - 1;
                int base = 0;
                if (lane == leader) base = atomicAdd(&g_nsel, __popc(mask));
                base = __shfl_sync(0xFFFFFFFFu, base, leader);
                if (keep) {
                    const int off = __popc(mask & ((1u << lane) - 1u));
                    if (base + off < SELCAP) g_sel[base + off] = key;
                }
            }
        }
    }
    gbar();

    // ========== phase 4: rank (one warp/survivor) + emit + fused gather =========
    {
        const int nsel = min(__ldcg(&g_nsel), SELCAP);
        for (int i = tid; i < nsel; i += NT) sm.rank.keys[i] = __ldcg(&g_sel[i]);
        __syncthreads();
        const int w = tid >> 5, lane = tid & 31;
        const int gi = w * NB + blockIdx.x;  // strided: spreads gather over blocks
        if (gi < nsel) {
            const unsigned long long key = sm.rank.keys[gi];
            unsigned int r = 0;
            for (int j = lane; j < nsel; j += 32)
                r += (sm.rank.keys[j] > key) ? 1u : 0u;
            r = __reduce_add_sync(0xFFFFFFFFu, r);   // exact rank, keys unique
            if (r < K) {
                const unsigned int hi = (unsigned int)(key >> 32);
                const unsigned int idx = 0xFFFFFFFFu - (unsigned int)key;
                if (lane == 0) {
                    out[OUT_KP + 2 * r + 0] = (float)(idx & (W - 1));
                    out[OUT_KP + 2 * r + 1] = (float)(idx >> 10);
                    out[OUT_SC + r] = __uint_as_float(hi & 0x7FFFFFFFu);
                    out[OUT_VALID + r] = 1.0f;
                }
                // fused descriptor gather + L2 normalize (4 channels per lane)
                float v0 = __ldg(&feat[(size_t)(lane)*(H * W) + idx]);
                float v1 = __ldg(&feat[(size_t)(lane + 32) * (H * W) + idx]);
                float v2 = __ldg(&feat[(size_t)(lane + 64) * (H * W) + idx]);
                float v3 = __ldg(&feat[(size_t)(lane + 96) * (H * W) + idx]);
                float ss = v0 * v0 + v1 * v1 + v2 * v2 + v3 * v3;
#pragma unroll
                for (int o = 16; o > 0; o >>= 1)
                    ss += __shfl_xor_sync(0xFFFFFFFFu, ss, o);
                const float inorm = 1.0f / fmaxf(sqrtf(ss), 1e-12f);
                float* drow = out + OUT_D + (size_t)r * D;
                drow[lane] = v0 * inorm;
                drow[lane + 32] = v1 * inorm;
                drow[lane + 64] = v2 * inorm;
                drow[lane + 96] = v3 * inorm;
            }
        } else if (gi < K) {  // padding rows when nsel < K (rows nsel..K-1)
            if (lane == 0) {
                out[OUT_KP + 2 * gi + 0] = 0.0f;
                out[OUT_KP + 2 * gi + 1] = 0.0f;
                out[OUT_SC + gi] = NEG_INF;
                out[OUT_VALID + gi] = 0.0f;
            }
            float* drow = out + OUT_D + (size_t)gi * D;
            drow[lane] = 0.0f;
            drow[lane + 32] = 0.0f;
            drow[lane + 64] = 0.0f;
            drow[lane + 96] = 0.0f;
        }
    }

    // ========== tail: last block to finish re-zeros ALL state for next replay ===
    __syncthreads();
    if (tid == 0) {
        __threadfence();
        slast = (atomicAdd(&g_done, 1u) == NB - 1) ? 1 : 0;
    }
    __syncthreads();
    if (slast) {
        for (int i = tid; i < 2048; i += NT) {   // FIX: full stride loop, all bins
            g_hist1[i] = 0u;
            g_hist2[i] = 0u;
        }
        __syncthreads();
        if (tid == 0) { g_ncand = 0; g_nsel = 0; __threadfence(); g_done = 0u; }
    }
}

// ---------------- launch ---------------------------------------------------------
extern "C" void kernel_launch(void* const* d_in, const int* in_sizes, int n_in,
                              void* d_out, int out_size) {
    const float* feat = (const float*)d_in[0];
    const int* ow_p = (n_in > 1) ? (const int*)d_in[1] : nullptr;
    const int* oh_p = (n_in > 2) ? (const int*)d_in[2] : nullptr;
    float* out = (float*)d_out;
    disk_mega<<<NB, NT>>>(feat, ow_p, oh_p, out);
}